// round 6
// baseline (speedup 1.0000x reference)
#include <cuda_runtime.h>
#include <cstdint>

// Problem constants
#define BATCH   4
#define SEQ     2048
#define CDIM    1024
#define NHEAD   16
#define DHEAD   64
#define MROWS   (BATCH * SEQ)          // 8192
#define BH      (BATCH * NHEAD)        // 64

// Scratch (device globals; no allocations allowed)
__device__ float g_q[(size_t)BH * SEQ * DHEAD];   // [BH][T][D]
__device__ float g_k[(size_t)BH * SEQ * DHEAD];
__device__ float g_v[(size_t)BH * SEQ * DHEAD];
__device__ float g_y[(size_t)MROWS * CDIM];       // [B,T,C], tf32-rounded
__device__ float g_xr[(size_t)MROWS * CDIM];      // x, tf32-rounded
__device__ float g_wt1[(size_t)3072 * 1024];      // w_attn^T, tf32-rounded
__device__ float g_wt2[(size_t)1024 * 1024];      // w_proj^T, tf32-rounded

// ---------------------------------------------------------------------------
// Helpers
// ---------------------------------------------------------------------------
__device__ __forceinline__ uint32_t smem_u32(const void* p) {
    uint32_t a;
    asm("{ .reg .u64 t; cvta.to.shared.u64 t, %1; cvt.u32.u64 %0, t; }" : "=r"(a) : "l"(p));
    return a;
}
__device__ __forceinline__ float to_tf32(float x) {
    float r;
    asm("cvt.rna.tf32.f32 %0, %1;" : "=f"(r) : "f"(x));
    return r;
}
__device__ __forceinline__ void cp16(uint32_t smem_dst, const void* gsrc) {
    asm volatile("cp.async.cg.shared.global [%0], [%1], 16;" :: "r"(smem_dst), "l"(gsrc));
}
#define CP_COMMIT() asm volatile("cp.async.commit_group;" ::: "memory")
#define CP_WAIT(N)  asm volatile("cp.async.wait_group %0;" :: "n"(N) : "memory")

// m16n8k8 tf32 MMA (row.col), fp32 accumulate
__device__ __forceinline__ void mma_tf32(float c[4], const float a[4], const float b[2]) {
    asm volatile(
        "mma.sync.aligned.m16n8k8.row.col.f32.tf32.tf32.f32 "
        "{%0,%1,%2,%3}, {%4,%5,%6,%7}, {%8,%9}, {%0,%1,%2,%3};\n"
        : "+f"(c[0]), "+f"(c[1]), "+f"(c[2]), "+f"(c[3])
        : "r"(__float_as_uint(a[0])), "r"(__float_as_uint(a[1])),
          "r"(__float_as_uint(a[2])), "r"(__float_as_uint(a[3])),
          "r"(__float_as_uint(b[0])), "r"(__float_as_uint(b[1])));
}

// ---------------------------------------------------------------------------
// Pre-pass kernels: tf32 rounding (+transpose for weights)
// ---------------------------------------------------------------------------
__global__ __launch_bounds__(256)
void round_copy(const float* __restrict__ src, float* __restrict__ dst)
{
    int i = blockIdx.x * blockDim.x + threadIdx.x;
    float4 v = ((const float4*)src)[i];
    v.x = to_tf32(v.x); v.y = to_tf32(v.y);
    v.z = to_tf32(v.z); v.w = to_tf32(v.w);
    ((float4*)dst)[i] = v;
}

__global__ __launch_bounds__(256)
void transpose_round(const float* __restrict__ W, float* __restrict__ WT, int N)
{
    __shared__ float tile[32][33];
    int n0 = blockIdx.x * 32;
    int k0 = blockIdx.y * 32;
    int tx = threadIdx.x, ty = threadIdx.y;     // 32 x 8
#pragma unroll
    for (int i = ty; i < 32; i += 8)
        tile[i][tx] = W[(size_t)(k0 + i) * N + n0 + tx];
    __syncthreads();
#pragma unroll
    for (int i = ty; i < 32; i += 8)
        WT[(size_t)(n0 + i) * 1024 + k0 + tx] = to_tf32(tile[tx][i]);
}

// ---------------------------------------------------------------------------
// tf32 mma.sync GEMM: out[M,N] = A[M,1024] @ W[1024,N] + bias
// 128x128 CTA tile, 4 warps of 64x64 output each, BK=16, 3-stage cp.async
// pipeline, one __syncthreads per slab. Target 2 CTAs/SM.
// ---------------------------------------------------------------------------
#define PITCH_G 20
#define STG_FLOATS (128 * PITCH_G)                // 2560 floats per matrix
#define GEMM_SMEM  (3 * 2 * STG_FLOATS * 4)       // 61,440 B

template <bool SCATTER>
__global__ __launch_bounds__(128, 2)
void gemm_mma(const float* __restrict__ A, const float* __restrict__ BT,
              const float* __restrict__ bias, float* __restrict__ out)
{
    extern __shared__ float smg[];

    const int tid = threadIdx.x;
    const int wid = tid >> 5;
    const int lane = tid & 31;
    const int wr = wid >> 1;         // 0..1  (64 M rows each)
    const int wc = wid & 1;          // 0..1  (64 N cols each)
    const int c0 = blockIdx.x * 128;
    const int r0 = blockIdx.y * 128;

    const float* Ab = A + (size_t)r0 * 1024;
    const float* Bb = BT + (size_t)c0 * 1024;

    float acc[4][8][4];
#pragma unroll
    for (int mt = 0; mt < 4; mt++)
#pragma unroll
        for (int nt = 0; nt < 8; nt++)
#pragma unroll
            for (int u = 0; u < 4; u++) acc[mt][nt][u] = 0.f;

    auto stage = [&](int c, int st) {
        float* sA = smg + st * 2 * STG_FLOATS;
        float* sB = sA + STG_FLOATS;
        const int k0 = c * 16;
#pragma unroll
        for (int i = 0; i < 4; i++) {
            int slot = tid + i * 128;        // 0..511
            int row = slot >> 2;             // 0..127
            int kq = (slot & 3) * 4;         // 0,4,8,12
            cp16(smem_u32(&sA[row * PITCH_G + kq]),
                 Ab + (size_t)row * 1024 + k0 + kq);
            cp16(smem_u32(&sB[row * PITCH_G + kq]),
                 Bb + (size_t)row * 1024 + k0 + kq);
        }
        CP_COMMIT();
    };

    stage(0, 0);
    stage(1, 1);

    const int lr = lane >> 2;        // 0..7
    const int lk = lane & 3;         // 0..3

    for (int c = 0; c < 64; c++) {
        const int st = c % 3;
        CP_WAIT(1);                  // slab c resident
        __syncthreads();             // visibility + everyone done with stage st
        if (c + 2 < 64) stage(c + 2, (c + 2) % 3);
        else CP_COMMIT();            // keep group accounting aligned

        const float* tA = smg + st * 2 * STG_FLOATS + wr * 64 * PITCH_G;
        const float* tB = smg + st * 2 * STG_FLOATS + STG_FLOATS + wc * 64 * PITCH_G;
#pragma unroll
        for (int ks = 0; ks < 2; ks++) {
            float b[8][2];
#pragma unroll
            for (int nt = 0; nt < 8; nt++) {
                const float* Bn = &tB[(nt * 8 + lr) * PITCH_G + ks * 8];
                b[nt][0] = Bn[lk];
                b[nt][1] = Bn[4 + lk];
            }
#pragma unroll
            for (int mt = 0; mt < 4; mt++) {
                const float* Am = &tA[(mt * 16 + lr) * PITCH_G + ks * 8];
                float a[4];
                a[0] = Am[lk];
                a[1] = Am[8 * PITCH_G + lk];
                a[2] = Am[4 + lk];
                a[3] = Am[8 * PITCH_G + 4 + lk];
#pragma unroll
                for (int nt = 0; nt < 8; nt++)
                    mma_tf32(acc[mt][nt], a, b[nt]);
            }
        }
    }

    // Epilogue
    const int lc = (lane & 3) * 2;
#pragma unroll
    for (int mt = 0; mt < 4; mt++) {
#pragma unroll
        for (int nt = 0; nt < 8; nt++) {
            int m = r0 + wr * 64 + mt * 16 + lr;
            int n = c0 + wc * 64 + nt * 8 + lc;
            float b0 = bias[n], b1 = bias[n + 1];
            float2 v0 = make_float2(acc[mt][nt][0] + b0, acc[mt][nt][1] + b1);
            float2 v1 = make_float2(acc[mt][nt][2] + b0, acc[mt][nt][3] + b1);
            if (SCATTER) {
                int which = n >> 10;
                int cc = n & 1023;
                int h = cc >> 6;
                int d = cc & 63;
                int bb = m >> 11;
                int t = m & 2047;
                float* dst = (which == 0) ? g_q : (which == 1) ? g_k : g_v;
                size_t base = (size_t)(bb * NHEAD + h) * SEQ;
                *(float2*)(dst + (base + t) * DHEAD + d) = v0;
                *(float2*)(dst + (base + t + 8) * DHEAD + d) = v1;
            } else {
                *(float2*)(out + (size_t)m * 1024 + n) = v0;
                *(float2*)(out + (size_t)(m + 8) * 1024 + n) = v1;
            }
        }
    }
}

// ---------------------------------------------------------------------------
// Tensor-core flash attention (tf32 mma.sync)
// grid (16, 64): one CTA per (q-tile of 128 rows, bh). 8 warps x 16 Q rows.
// K double-buffered via cp.async; V transposed in smem [d][s] via
// register-prefetched LDG + STS.128 (conflict-free PV fragment loads).
// One __syncthreads per K tile. Scale folded into Q fragments.
// ---------------------------------------------------------------------------
#define AP 68
#define SMEM_ATTN ((2 * 64 + 2 * 64 + 128) * AP * 4)   // 104,448 B

__global__ __launch_bounds__(256)
void attn_mma()
{
    extern __shared__ float sm[];
    float* sK[2]  = {sm, sm + 64 * AP};
    float* sVt[2] = {sm + 2 * 64 * AP, sm + 3 * 64 * AP};   // [d][s]
    float* sP = sm + 4 * 64 * AP;     // [128][AP] per-warp-private rows

    const int qi = (int)gridDim.x - 1 - (int)blockIdx.x;   // heavy tiles first
    const int bh = blockIdx.y;
    const int tid = threadIdx.x;
    const int wid = tid >> 5;
    const int lane = tid & 31;
    const int lr = lane >> 2;        // 0..7
    const int lk = lane & 3;         // 0..3
    const int warp_m = wid * 16;
    const int q0 = qi * 128;

    const float* Kg = g_k + (size_t)bh * SEQ * DHEAD;
    const float* Vg = g_v + (size_t)bh * SEQ * DHEAD;

    // K tile via cp.async (natural [s][d])
    auto stageK = [&](int kt, int b) {
#pragma unroll
        for (int i = 0; i < 2; i++) {
            int slot = tid + i * 256;        // 0..511 float4 slots (64x16)
            int row = slot >> 3;             // 0..63
            int c4 = (slot & 7) * 8;         // 0,8,..56 -- two float4 each? no:
            (void)c4;
        }
        const int k0 = kt * 64;
#pragma unroll
        for (int i = 0; i < 4; i++) {
            int slot = tid + i * 256;        // 0..1023
            int row = slot >> 4;             // 0..63
            int c4 = (slot & 15) * 4;        // 0..60
            cp16(smem_u32(&sK[b][row * AP + c4]), Kg + (size_t)(k0 + row) * 64 + c4);
        }
        CP_COMMIT();
    };

    // V tile: LDG.32 gather of columns into registers (prefetch), then STS.128
    float4 vr[4];
    auto ldgV = [&](int kt) {
        const int k0 = kt * 64;
#pragma unroll
        for (int i = 0; i < 4; i++) {
            int slot = tid + i * 256;        // 0..1023
            int d = slot & 63;
            int s0 = (slot >> 6) * 4;        // 0..60
            const float* p = Vg + (size_t)(k0 + s0) * 64 + d;
            vr[i].x = p[0];
            vr[i].y = p[64];
            vr[i].z = p[128];
            vr[i].w = p[192];
        }
    };
    auto stsV = [&](int b) {
#pragma unroll
        for (int i = 0; i < 4; i++) {
            int slot = tid + i * 256;
            int d = slot & 63;
            int s0 = (slot >> 6) * 4;
            *(float4*)&sVt[b][d * AP + s0] = vr[i];
        }
    };

    // Q fragments (scale folded in): A-frag per k-step (8 steps of k=8)
    const float scale = 0.125f;      // 1/sqrt(64)
    float qf[8][4];
    {
        const float* Qw = g_q + ((size_t)bh * SEQ + q0 + warp_m) * DHEAD;
#pragma unroll
        for (int ks = 0; ks < 8; ks++) {
            qf[ks][0] = to_tf32(Qw[lr * 64 + ks * 8 + lk] * scale);
            qf[ks][1] = to_tf32(Qw[(lr + 8) * 64 + ks * 8 + lk] * scale);
            qf[ks][2] = to_tf32(Qw[lr * 64 + ks * 8 + 4 + lk] * scale);
            qf[ks][3] = to_tf32(Qw[(lr + 8) * 64 + ks * 8 + 4 + lk] * scale);
        }
    }

    float o[8][4];
#pragma unroll
    for (int nt = 0; nt < 8; nt++)
#pragma unroll
        for (int u = 0; u < 4; u++) o[nt][u] = 0.f;

    float m0 = -1e30f, m1 = -1e30f, l0 = 0.f, l1 = 0.f;
    const int row0 = q0 + warp_m + lr;
    const int row1 = row0 + 8;

    float* Pr0 = &sP[(warp_m + lr) * AP];
    float* Pr1 = &sP[(warp_m + lr + 8) * AP];

    const int nkt = (qi + 1) * 2;
    stageK(0, 0);
    ldgV(0);

    for (int kt = 0; kt < nkt; kt++) {
        const int buf = kt & 1;
        const int k0 = kt * 64;

        stsV(buf);                   // V tile kt -> smem (buffer free: consumed
                                     // at kt-2, guaranteed by barrier kt-1)
        CP_WAIT(0);                  // K tile kt resident
        __syncthreads();             // visibility of K cp.async + V STS

        if (kt + 1 < nkt) {
            ldgV(kt + 1);            // register prefetch, hidden by compute
            stageK(kt + 1, buf ^ 1); // buffer consumed at kt-1: safe post-barrier
        } else {
            CP_COMMIT();
        }

        // Warps fully above the diagonal of this K tile: staging duty only
        if (k0 > q0 + warp_m + 15) continue;

        const float* cK = sK[buf];
        const float* cV = sVt[buf];

        // S = Q K^T   (16 x 64 per warp)
        float s[8][4];
#pragma unroll
        for (int nt = 0; nt < 8; nt++)
#pragma unroll
            for (int u = 0; u < 4; u++) s[nt][u] = 0.f;

#pragma unroll
        for (int nt = 0; nt < 8; nt++) {
            const float* Kn = &cK[(nt * 8 + lr) * AP];
#pragma unroll
            for (int ks = 0; ks < 8; ks++) {
                float b[2] = {Kn[ks * 8 + lk], Kn[ks * 8 + 4 + lk]};
                mma_tf32(s[nt], qf[ks], b);
            }
        }

        // Causal mask (scale already folded into Q) + row max
        const bool need_mask = (k0 + 63 > row0);
        float rmax0 = -1e30f, rmax1 = -1e30f;
#pragma unroll
        for (int nt = 0; nt < 8; nt++) {
            if (need_mask) {
                const int cb = k0 + nt * 8 + 2 * lk;
                if (cb     > row0) s[nt][0] = -1e30f;
                if (cb + 1 > row0) s[nt][1] = -1e30f;
                if (cb     > row1) s[nt][2] = -1e30f;
                if (cb + 1 > row1) s[nt][3] = -1e30f;
            }
            rmax0 = fmaxf(rmax0, fmaxf(s[nt][0], s[nt][1]));
            rmax1 = fmaxf(rmax1, fmaxf(s[nt][2], s[nt][3]));
        }
        rmax0 = fmaxf(rmax0, __shfl_xor_sync(0xffffffffu, rmax0, 1));
        rmax0 = fmaxf(rmax0, __shfl_xor_sync(0xffffffffu, rmax0, 2));
        rmax1 = fmaxf(rmax1, __shfl_xor_sync(0xffffffffu, rmax1, 1));
        rmax1 = fmaxf(rmax1, __shfl_xor_sync(0xffffffffu, rmax1, 2));

        const float mn0 = fmaxf(m0, rmax0);
        const float mn1 = fmaxf(m1, rmax1);
        const float a0 = __expf(m0 - mn0);
        const float a1 = __expf(m1 - mn1);
        m0 = mn0; m1 = mn1;

        float rs0 = 0.f, rs1 = 0.f;
#pragma unroll
        for (int nt = 0; nt < 8; nt++) {
            s[nt][0] = __expf(s[nt][0] - mn0);
            s[nt][1] = __expf(s[nt][1] - mn0);
            s[nt][2] = __expf(s[nt][2] - mn1);
            s[nt][3] = __expf(s[nt][3] - mn1);
            rs0 += s[nt][0] + s[nt][1];
            rs1 += s[nt][2] + s[nt][3];
        }
        rs0 += __shfl_xor_sync(0xffffffffu, rs0, 1);
        rs0 += __shfl_xor_sync(0xffffffffu, rs0, 2);
        rs1 += __shfl_xor_sync(0xffffffffu, rs1, 1);
        rs1 += __shfl_xor_sync(0xffffffffu, rs1, 2);
        l0 = l0 * a0 + rs0;
        l1 = l1 * a1 + rs1;

#pragma unroll
        for (int nt = 0; nt < 8; nt++) {
            o[nt][0] *= a0; o[nt][1] *= a0;
            o[nt][2] *= a1; o[nt][3] *= a1;
        }

        // P -> per-warp-private smem strip (tf32-rounded)
#pragma unroll
        for (int nt = 0; nt < 8; nt++) {
            *(float2*)&Pr0[nt * 8 + 2 * lk] =
                make_float2(to_tf32(s[nt][0]), to_tf32(s[nt][1]));
            *(float2*)&Pr1[nt * 8 + 2 * lk] =
                make_float2(to_tf32(s[nt][2]), to_tf32(s[nt][3]));
        }
        __syncwarp();

        // O += P @ V   (V transposed: B[n][k] = sVt[n*AP + k], conflict-free)
#pragma unroll
        for (int ks = 0; ks < 8; ks++) {
            float ap[4];
            ap[0] = Pr0[ks * 8 + lk];
            ap[1] = Pr1[ks * 8 + lk];
            ap[2] = Pr0[ks * 8 + 4 + lk];
            ap[3] = Pr1[ks * 8 + 4 + lk];
#pragma unroll
            for (int nt = 0; nt < 8; nt++) {
                const float* Vn = &cV[(nt * 8 + lr) * AP];
                float b[2] = {Vn[ks * 8 + lk], Vn[ks * 8 + 4 + lk]};
                mma_tf32(o[nt], ap, b);
            }
        }
        __syncwarp();
    }

    // Epilogue: normalize, tf32-round (feeds tf32 proj GEMM), write [B,T,C]
    const float inv0 = 1.f / l0;
    const float inv1 = 1.f / l1;
    const int b = bh >> 4;
    const int h = bh & 15;
    float* y0 = g_y + ((size_t)(b * SEQ + row0)) * CDIM + h * 64;
    float* y1 = g_y + ((size_t)(b * SEQ + row1)) * CDIM + h * 64;
#pragma unroll
    for (int nt = 0; nt < 8; nt++) {
        int d = nt * 8 + 2 * lk;
        *(float2*)(y0 + d) = make_float2(to_tf32(o[nt][0] * inv0),
                                         to_tf32(o[nt][1] * inv0));
        *(float2*)(y1 + d) = make_float2(to_tf32(o[nt][2] * inv1),
                                         to_tf32(o[nt][3] * inv1));
    }
}

// ---------------------------------------------------------------------------
extern "C" void kernel_launch(void* const* d_in, const int* in_sizes, int n_in,
                              void* d_out, int out_size)
{
    const float* x      = (const float*)d_in[0];
    const float* w_attn = (const float*)d_in[1];
    const float* b_attn = (const float*)d_in[2];
    const float* w_proj = (const float*)d_in[3];
    const float* b_proj = (const float*)d_in[4];
    float* out = (float*)d_out;

    cudaFuncSetAttribute(attn_mma, cudaFuncAttributeMaxDynamicSharedMemorySize,
                         SMEM_ATTN);
    cudaFuncSetAttribute(gemm_mma<true>, cudaFuncAttributeMaxDynamicSharedMemorySize,
                         GEMM_SMEM);
    cudaFuncSetAttribute(gemm_mma<false>, cudaFuncAttributeMaxDynamicSharedMemorySize,
                         GEMM_SMEM);
    cudaFuncSetAttribute(gemm_mma<true>,
                         cudaFuncAttributePreferredSharedMemoryCarveout, 100);
    cudaFuncSetAttribute(gemm_mma<false>,
                         cudaFuncAttributePreferredSharedMemoryCarveout, 100);

    void* y_ptr = nullptr;   cudaGetSymbolAddress(&y_ptr, g_y);
    void* xr_ptr = nullptr;  cudaGetSymbolAddress(&xr_ptr, g_xr);
    void* wt1_ptr = nullptr; cudaGetSymbolAddress(&wt1_ptr, g_wt1);
    void* wt2_ptr = nullptr; cudaGetSymbolAddress(&wt2_ptr, g_wt2);

    // 0) tf32-round x; transpose + round weights
    round_copy<<<(MROWS * CDIM / 4) / 256, 256>>>(x, (float*)xr_ptr);
    transpose_round<<<dim3(3072 / 32, 1024 / 32), dim3(32, 8)>>>(w_attn, (float*)wt1_ptr, 3072);
    transpose_round<<<dim3(1024 / 32, 1024 / 32), dim3(32, 8)>>>(w_proj, (float*)wt2_ptr, 1024);

    // 1) QKV projection (tf32 mma) + scatter to [BH][T][D]
    gemm_mma<true><<<dim3(3072 / 128, MROWS / 128), 128, GEMM_SMEM>>>(
        (const float*)xr_ptr, (const float*)wt1_ptr, b_attn, nullptr);

    // 2) Causal flash attention (tf32 mma)
    attn_mma<<<dim3(SEQ / 128, BH), 256, SMEM_ATTN>>>();

    // 3) Output projection (tf32 mma)
    gemm_mma<false><<<dim3(1024 / 128, MROWS / 128), 128, GEMM_SMEM>>>(
        (const float*)y_ptr, (const float*)wt2_ptr, b_proj, out);
}